// round 16
// baseline (speedup 1.0000x reference)
#include <cuda_runtime.h>
#include <cuda_fp16.h>

#define N_NODES 100000
#define DIM     128
#define N_ANCH  4096
#define N_SAMP  512
// sim = dot_int / 127^2 ; arg = sim / TEMP = dot_int * (10 / 16129)
#define EXP_SCALE (10.0f / 16129.0f)

// Normalized feature table quantized to int8, 4 per int32:
// 100000 * 32 int32 = 12.8 MB (fits L2 easily). Row = 128B.
__device__ int g_xq[(size_t)N_NODES * (DIM / 4)];

// Kernel 1: warp per 4 rows -> L2-normalize, quantize to int8. Zero output.
__global__ void quantize_kernel(const float* __restrict__ x, float* __restrict__ out) {
    if (blockIdx.x == 0 && threadIdx.x == 0) out[0] = 0.0f;

    int quad = blockIdx.x * (blockDim.x >> 5) + (threadIdx.x >> 5);
    int row0 = quad * 4;
    if (row0 >= N_NODES) return;
    int lane = threadIdx.x & 31;

    float4 v[4];
    #pragma unroll
    for (int j = 0; j < 4; ++j) {
        int row = row0 + j;
        v[j] = (row < N_NODES)
             ? reinterpret_cast<const float4*>(x + (size_t)row * DIM)[lane]
             : make_float4(1.f, 0.f, 0.f, 0.f);
    }

    float s[4];
    #pragma unroll
    for (int j = 0; j < 4; ++j)
        s[j] = v[j].x * v[j].x + v[j].y * v[j].y + v[j].z * v[j].z + v[j].w * v[j].w;
    #pragma unroll
    for (int o = 16; o; o >>= 1) {
        #pragma unroll
        for (int j = 0; j < 4; ++j)
            s[j] += __shfl_xor_sync(0xffffffffu, s[j], o);
    }

    #pragma unroll
    for (int j = 0; j < 4; ++j) {
        int row = row0 + j;
        if (row >= N_NODES) break;
        float inv = rsqrtf(s[j]) * 127.0f;
        int q0 = __float2int_rn(v[j].x * inv);
        int q1 = __float2int_rn(v[j].y * inv);
        int q2 = __float2int_rn(v[j].z * inv);
        int q3 = __float2int_rn(v[j].w * inv);
        unsigned p = (unsigned)(q0 & 0xff) | ((unsigned)(q1 & 0xff) << 8)
                   | ((unsigned)(q2 & 0xff) << 16) | ((unsigned)(q3 & 0xff) << 24);
        g_xq[(size_t)row * (DIM / 4) + lane] = (int)p;
    }
}

// Kernel 2: one block per anchor, 8 warps. All 64 rows per warp are staged
// into smem via cp.async (2 commit groups of 32 rows) — up to 64 rows in
// flight per warp with ZERO register cost. Compute for group 0 overlaps
// group 1's L2 round-trip. Each warp consumes only its own staged rows.
// Smem staging: 8 warps * 64 rows * 128B = 64KB dynamic.
__global__ __launch_bounds__(256) void supcon_kernel(
    const int*   __restrict__ y,
    const int*   __restrict__ anchors,
    const int*   __restrict__ sampled,
    float*       __restrict__ out)
{
    extern __shared__ char stage[];          // 64KB: warp*8192 + it*4096 + slot*128
    __shared__ float s_num[8], s_den[8], s_cnt[8];

    const int a    = blockIdx.x;
    const int lane = threadIdx.x & 31;
    const int warp = threadIdx.x >> 5;
    const int grp  = lane >> 3;     // group 0..3
    const int gl   = lane & 7;      // lane within group (16B slice of the row)
    // Sample-within-group this lane will own after the packed fold.
    const int sig  = (((lane >> 2) & 1)) | (((lane >> 1) & 1) << 1) | ((lane & 1) << 2);

    const int anchor = anchors[a];
    const int ya     = y[anchor];

    const int4* xq4 = reinterpret_cast<const int4*>(g_xq);
    const int4  a4  = xq4[(size_t)anchor * 8 + gl];

    const int* samp = sampled + (size_t)a * N_SAMP;

    // Both iterations' sample indices (1 reg each) + owned labels prefetched.
    const int idx_l0 = samp[warp * 32 + lane];
    const int idx_l1 = samp[256 + warp * 32 + lane];
    const int my_y0  = y[__shfl_sync(0xffffffffu, idx_l0, sig * 4 + grp)];
    const int my_y1  = y[__shfl_sync(0xffffffffu, idx_l1, sig * 4 + grp)];

    // Stage all 64 rows via cp.async: 8 warp-instructions per group of 32.
    const char* gbase = reinterpret_cast<const char*>(g_xq);
    unsigned wbase = (unsigned)__cvta_generic_to_shared(stage) + warp * 8192 + gl * 16;

    #pragma unroll
    for (int it = 0; it < 2; ++it) {
        const int idx_lane = it ? idx_l1 : idx_l0;
        #pragma unroll
        for (int j = 0; j < 8; ++j) {
            int row = __shfl_sync(0xffffffffu, idx_lane, j * 4 + grp);
            const char* src = gbase + (size_t)row * 128 + gl * 16;
            unsigned dst = wbase + it * 4096 + (j * 4 + grp) * 128;
            asm volatile("cp.async.cg.shared.global [%0], [%1], 16;\n"
                         :: "r"(dst), "l"(src));
        }
        asm volatile("cp.async.commit_group;\n");
    }

    float num = 0.0f, den = 0.0f, cnt = 0.0f;

    #pragma unroll
    for (int it = 0; it < 2; ++it) {
        if (it == 0)
            asm volatile("cp.async.wait_group 1;\n" ::: "memory");
        else
            asm volatile("cp.async.wait_group 0;\n" ::: "memory");

        const int my_y = it ? my_y1 : my_y0;

        // Read staged rows: 8 LDS.128, conflict-free (512B contiguous/warp).
        const char* sb = stage + warp * 8192 + it * 4096 + gl * 16;
        int4 sv[8];
        #pragma unroll
        for (int j = 0; j < 8; ++j)
            sv[j] = *reinterpret_cast<const int4*>(sb + (j * 4 + grp) * 128);

        int d[8];
        #pragma unroll
        for (int j = 0; j < 8; ++j)
            d[j] = __dp4a(a4.x, sv[j].x,
                   __dp4a(a4.y, sv[j].y,
                   __dp4a(a4.z, sv[j].z,
                   __dp4a(a4.w, sv[j].w, 0))));

        // Packed select-fold within each 8-lane group: 7 shuffles, exact int.
        int e4[4];
        #pragma unroll
        for (int j = 0; j < 4; ++j) {
            int t = (gl & 4) ? d[2*j] : d[2*j + 1];
            int r = __shfl_xor_sync(0xffffffffu, t, 4);
            e4[j] = ((gl & 4) ? d[2*j + 1] : d[2*j]) + r;
        }
        int f2[2];
        #pragma unroll
        for (int j = 0; j < 2; ++j) {
            int t = (gl & 2) ? e4[2*j] : e4[2*j + 1];
            int r = __shfl_xor_sync(0xffffffffu, t, 2);
            f2[j] = ((gl & 2) ? e4[2*j + 1] : e4[2*j]) + r;
        }
        int t1 = (gl & 1) ? f2[0] : f2[1];
        int r1 = __shfl_xor_sync(0xffffffffu, t1, 1);
        int g  = ((gl & 1) ? f2[1] : f2[0]) + r1;
        // g = full int dot of sample (it*256 + warp*32 + sig*4 + grp).

        const float e = __expf(__int2float_rn(g) * EXP_SCALE);
        den += e;
        if (my_y == ya) { num += e; cnt += 1.0f; }
    }

    // Warp reduce (each sample counted exactly once across the warp).
    #pragma unroll
    for (int o = 16; o; o >>= 1) {
        den += __shfl_xor_sync(0xffffffffu, den, o);
        num += __shfl_xor_sync(0xffffffffu, num, o);
        cnt += __shfl_xor_sync(0xffffffffu, cnt, o);
    }
    if (lane == 0) { s_num[warp] = num; s_den[warp] = den; s_cnt[warp] = cnt; }
    __syncthreads();

    if (threadIdx.x == 0) {
        float tn = 0.0f, td = 0.0f, tc = 0.0f;
        #pragma unroll
        for (int w = 0; w < 8; w++) { tn += s_num[w]; td += s_den[w]; tc += s_cnt[w]; }
        float loss = 0.0f;
        if (tc > 0.0f) loss = -logf(tn / td) / tc;
        atomicAdd(out, loss);
    }
}

extern "C" void kernel_launch(void* const* d_in, const int* in_sizes, int n_in,
                              void* d_out, int out_size) {
    const float* x       = (const float*)d_in[0];
    const int*   y       = (const int*)  d_in[1];
    const int*   anchors = (const int*)  d_in[2];
    const int*   sampled = (const int*)  d_in[3];
    float*       out     = (float*)d_out;

    const int wpb = 8;                       // warps per block, 4 rows each
    const int quads = (N_NODES + 3) / 4;
    const int blocks = (quads + wpb - 1) / wpb;
    quantize_kernel<<<blocks, wpb * 32>>>(x, out);

    const int stage_bytes = 8 * 64 * 128;    // 64KB dynamic smem
    cudaFuncSetAttribute(supcon_kernel,
                         cudaFuncAttributeMaxDynamicSharedMemorySize, stage_bytes);
    supcon_kernel<<<N_ANCH, 256, stage_bytes>>>(y, anchors, sampled, out);
}